// round 3
// baseline (speedup 1.0000x reference)
#include <cuda_runtime.h>

#define FULL 0xFFFFFFFFu

// feat[b][n] scratch (64*1024 floats) + ticket counter. __device__ globals
// are the allowed scratch mechanism (no allocation).
__device__ float g_feat[64 * 1024];
__device__ unsigned int g_ticket = 0;

__global__ __launch_bounds__(256) void fused_kernel(
    const float* __restrict__ x,
    const float* __restrict__ w1, const float* __restrict__ b1,
    const float* __restrict__ w2, const float* __restrict__ b2,
    const float* __restrict__ w3, const float* __restrict__ b3,
    const float* __restrict__ cw, const float* __restrict__ cb,
    float* __restrict__ out)
{
    // 8 warps per block, one row (b,n) per warp.
    __shared__ float sm[8][152];   // 150->30 pool redistribution
    __shared__ float sW[20];       // all conv weights/biases, loaded once/block
    __shared__ int   sLast;

    const int tid  = threadIdx.x;
    const int warp = tid >> 5;
    const int lane = tid & 31;
    const int row  = blockIdx.x * 8 + warp;   // row in [0, 65536)

    const float4* X4 = reinterpret_cast<const float4*>(x + (size_t)row * 1200);

    // ---- issue the 10 data LDG.128s per lane FIRST (MLP=10, overlaps barrier)
    float4 A0[5], A1[5];
    #pragma unroll
    for (int it = 0; it < 5; it++) {
        int j  = it * 32 + lane;
        int jj = j < 150 ? j : 149;          // clamp (it==4 lanes 22..31 idle)
        A0[it] = X4[2 * jj];
        A1[it] = X4[2 * jj + 1];
    }

    // ---- stage all weights into smem once per block (kills ~20 uniform
    //      LDG wavefronts per row; LDS broadcast is conflict-free)
    if (tid < 10)       sW[tid] = w1[tid];
    else if (tid == 10) sW[10]  = b1[0];
    else if (tid < 14)  sW[tid] = w2[tid - 11];
    else if (tid == 14) sW[14]  = b2[0];
    else if (tid < 19)  sW[tid] = w3[tid - 15];
    else if (tid == 19) sW[19]  = b3[0];
    __syncthreads();

    float W1[10];
    #pragma unroll
    for (int k = 0; k < 10; k++) W1[k] = sW[k];
    const float B1 = sW[10];

    // ---- conv1: K=10, stride=8, pad=1, out length 150, relu
    float y[5];
    float carry = 0.0f;                      // x[8j-1] carry (x[-1] = left pad)
    #pragma unroll
    for (int it = 0; it < 5; it++) {
        // x[8j-1] = elem 8(j-1)+7 = previous lane's A1.w
        float xm1 = __shfl_up_sync(FULL, A1[it].w, 1);
        if (lane == 0) xm1 = carry;
        carry = __shfl_sync(FULL, A1[it].w, 31);

        // x[8j+8] = next lane's A0.x; lane 31 takes next iter's lane-0 A0.x
        float nxt = (it < 4) ? __shfl_sync(FULL, A0[it + 1].x, 0) : 0.0f;
        float a2  = __shfl_down_sync(FULL, A0[it].x, 1);
        if (lane == 31) a2 = nxt;
        int j = it * 32 + lane;
        if (j == 149) a2 = 0.0f;             // right pad

        float v = B1;
        v = fmaf(W1[0], xm1,      v);
        v = fmaf(W1[1], A0[it].x, v);
        v = fmaf(W1[2], A0[it].y, v);
        v = fmaf(W1[3], A0[it].z, v);
        v = fmaf(W1[4], A0[it].w, v);
        v = fmaf(W1[5], A1[it].x, v);
        v = fmaf(W1[6], A1[it].y, v);
        v = fmaf(W1[7], A1[it].z, v);
        v = fmaf(W1[8], A1[it].w, v);
        v = fmaf(W1[9], a2,       v);
        y[it] = fmaxf(v, 0.0f);
    }

    // ---- stash y1 (150 vals) in smem for the stride-5 pool gather
    float* S = sm[warp];
    #pragma unroll
    for (int it = 0; it < 5; it++) {
        int j = it * 32 + lane;
        if (j < 150) S[j] = y[it];
    }
    __syncwarp();

    // ---- maxpool k=5 s=5 (150 -> 30); relu no-op (inputs >= 0)
    float p = 0.0f;
    if (lane < 30) {
        p = S[5 * lane];
        #pragma unroll
        for (int k = 1; k < 5; k++) p = fmaxf(p, S[5 * lane + k]);
    }

    // ---- conv2: K=3 s=3 (30 -> 10), relu
    const float w20 = sW[11], w21 = sW[12], w22 = sW[13], B2 = sW[14];
    float pa = __shfl_sync(FULL, p, (3 * lane)     & 31);
    float pb = __shfl_sync(FULL, p, (3 * lane + 1) & 31);
    float pc = __shfl_sync(FULL, p, (3 * lane + 2) & 31);
    float q = fmaxf(fmaf(w20, pa, fmaf(w21, pb, fmaf(w22, pc, B2))), 0.0f);

    // ---- maxpool k=3 s=3 pad=1 (10 -> 4); relu no-op
    float qm = __shfl_sync(FULL, q, (3 * lane - 1) & 31);
    float q0 = __shfl_sync(FULL, q, (3 * lane)     & 31);
    float qp = __shfl_sync(FULL, q, (3 * lane + 1) & 31);
    float r;
    if (lane == 0)      r = fmaxf(q0, qp);
    else if (lane == 3) r = fmaxf(qm, q0);
    else                r = fmaxf(fmaxf(qm, q0), qp);

    // ---- conv3: K=4 s=1 (4 -> 1), relu -> feat
    float r0 = __shfl_sync(FULL, r, 0);
    float r1 = __shfl_sync(FULL, r, 1);
    float r2 = __shfl_sync(FULL, r, 2);
    float r3 = __shfl_sync(FULL, r, 3);
    if (lane == 0) {
        float f = sW[19];
        f = fmaf(sW[15], r0, f);
        f = fmaf(sW[16], r1, f);
        f = fmaf(sW[17], r2, f);
        f = fmaf(sW[18], r3, f);
        g_feat[row] = fmaxf(f, 0.0f);
    }

    // ---- last-block-done head (deterministic: identical math whoever is last)
    __syncthreads();
    if (tid == 0) {
        __threadfence();
        unsigned t = atomicAdd(&g_ticket, 1u);
        sLast = (t == gridDim.x - 1) ? 1 : 0;
    }
    __syncthreads();
    if (!sLast) return;

    // Head: logits = feat @ cls_w.T + cls_b ; softmax over 3 classes.
    // Warp w handles batches 8w..8w+7; lanes stride float4 over 1024 nodes.
    const float4* c0 = reinterpret_cast<const float4*>(cw);
    const float4* c1 = reinterpret_cast<const float4*>(cw + 1024);
    const float4* c2 = reinterpret_cast<const float4*>(cw + 2048);
    #pragma unroll 1
    for (int bb = 0; bb < 8; bb++) {
        int b = warp * 8 + bb;
        const float4* f4 = reinterpret_cast<const float4*>(g_feat + b * 1024);
        float a0 = 0.f, a1 = 0.f, a2 = 0.f;
        #pragma unroll
        for (int i = 0; i < 8; i++) {
            int idx = lane + 32 * i;
            float4 fv = __ldcg(&f4[idx]);       // bypass L1: freshest data
            float4 u0 = __ldg(&c0[idx]);
            float4 u1 = __ldg(&c1[idx]);
            float4 u2 = __ldg(&c2[idx]);
            a0 = fmaf(fv.x,u0.x, fmaf(fv.y,u0.y, fmaf(fv.z,u0.z, fmaf(fv.w,u0.w, a0))));
            a1 = fmaf(fv.x,u1.x, fmaf(fv.y,u1.y, fmaf(fv.z,u1.z, fmaf(fv.w,u1.w, a1))));
            a2 = fmaf(fv.x,u2.x, fmaf(fv.y,u2.y, fmaf(fv.z,u2.z, fmaf(fv.w,u2.w, a2))));
        }
        #pragma unroll
        for (int o = 16; o > 0; o >>= 1) {
            a0 += __shfl_xor_sync(FULL, a0, o);
            a1 += __shfl_xor_sync(FULL, a1, o);
            a2 += __shfl_xor_sync(FULL, a2, o);
        }
        if (lane == 0) {
            float l0 = a0 + __ldg(&cb[0]);
            float l1 = a1 + __ldg(&cb[1]);
            float l2 = a2 + __ldg(&cb[2]);
            float m  = fmaxf(l0, fmaxf(l1, l2));
            float e0 = expf(l0 - m), e1 = expf(l1 - m), e2 = expf(l2 - m);
            float inv = 1.0f / (e0 + e1 + e2);
            out[b * 3 + 0] = e0 * inv;
            out[b * 3 + 1] = e1 * inv;
            out[b * 3 + 2] = e2 * inv;
        }
    }
    // reset ticket for the next graph replay
    if (tid == 0) g_ticket = 0;
}

extern "C" void kernel_launch(void* const* d_in, const int* in_sizes, int n_in,
                              void* d_out, int out_size)
{
    // metadata order: input, conv1_w, conv1_b, conv2_w, conv2_b, conv3_w,
    // conv3_b, gcn1_w, gcn1_b, gcn2_w, gcn2_b, cls_w, cls_b  (gcn* are dead)
    const float* x   = (const float*)d_in[0];
    const float* w1  = (const float*)d_in[1];
    const float* b1  = (const float*)d_in[2];
    const float* w2  = (const float*)d_in[3];
    const float* b2  = (const float*)d_in[4];
    const float* w3  = (const float*)d_in[5];
    const float* b3  = (const float*)d_in[6];
    const float* cw  = (const float*)d_in[11];
    const float* cb  = (const float*)d_in[12];
    float* out = (float*)d_out;

    fused_kernel<<<8192, 256>>>(x, w1, b1, w2, b2, w3, b3, cw, cb, out);
}

// round 5
// speedup vs baseline: 1.4888x; 1.4888x over previous
#include <cuda_runtime.h>

#define FULL 0xFFFFFFFFu

// feat[b][n] scratch (64*1024 floats). __device__ global = allowed scratch.
__device__ float g_feat[64 * 1024];

// 6 blocks/SM min -> ptxas caps regs at 42 -> 48 warps/SM (75% occ).
__global__ __launch_bounds__(256, 6) void conv_chain_kernel(
    const float* __restrict__ x,
    const float* __restrict__ w1, const float* __restrict__ b1,
    const float* __restrict__ w2, const float* __restrict__ b2,
    const float* __restrict__ w3, const float* __restrict__ b3)
{
    // 8 warps per block, one row (b,n) per warp.
    __shared__ float sm[8][152];   // conv1 output for the 150->30 pool gather

    const int warp = threadIdx.x >> 5;
    const int lane = threadIdx.x & 31;
    const int row  = blockIdx.x * 8 + warp;   // row in [0, 65536)

    const float4* X4 = reinterpret_cast<const float4*>(x + (size_t)row * 1200);
    float* S = sm[warp];

    // ---- conv1: K=10, stride=8, pad=1, out length 150, relu.
    // Output j = 32*it + lane, window x[8j-1 .. 8j+8].
    // Depth-2 software pipeline: only 4 float4s live at a time (low regs ->
    // high occupancy), while still keeping 4 LDG.128s in flight per lane.
    float4 a0, a1;
    {
        int jj = lane;                        // it=0: j = lane < 150 always
        a0 = X4[2 * jj];
        a1 = X4[2 * jj + 1];
    }

    float W1[10];
    #pragma unroll
    for (int k = 0; k < 10; k++) W1[k] = __ldg(&w1[k]);
    const float B1 = __ldg(b1);

    float carry = 0.0f;                       // x[8j-1] carry (x[-1] = pad)
    #pragma unroll
    for (int it = 0; it < 5; it++) {
        // prefetch next iteration's window
        float4 n0, n1;
        if (it < 4) {
            int j  = (it + 1) * 32 + lane;
            int jj = j < 150 ? j : 149;       // clamp (it==4 lanes 22..31 idle)
            n0 = X4[2 * jj];
            n1 = X4[2 * jj + 1];
        }

        // x[8j-1] = previous lane's a1.w
        float xm1 = __shfl_up_sync(FULL, a1.w, 1);
        if (lane == 0) xm1 = carry;
        carry = __shfl_sync(FULL, a1.w, 31);

        // x[8j+8] = next lane's a0.x; lane 31 takes next iter's lane-0 a0.x
        float nxt = (it < 4) ? __shfl_sync(FULL, n0.x, 0) : 0.0f;
        float a2  = __shfl_down_sync(FULL, a0.x, 1);
        if (lane == 31) a2 = nxt;
        int j = it * 32 + lane;
        if (j == 149) a2 = 0.0f;              // right pad

        float v = B1;
        v = fmaf(W1[0], xm1,  v);
        v = fmaf(W1[1], a0.x, v);
        v = fmaf(W1[2], a0.y, v);
        v = fmaf(W1[3], a0.z, v);
        v = fmaf(W1[4], a0.w, v);
        v = fmaf(W1[5], a1.x, v);
        v = fmaf(W1[6], a1.y, v);
        v = fmaf(W1[7], a1.z, v);
        v = fmaf(W1[8], a1.w, v);
        v = fmaf(W1[9], a2,   v);
        if (j < 150) S[j] = fmaxf(v, 0.0f);   // write y1 straight to smem

        a0 = n0; a1 = n1;
    }
    __syncwarp();

    // ---- maxpool k=5 s=5 (150 -> 30); relu no-op (inputs >= 0)
    float p = 0.0f;
    if (lane < 30) {
        p = S[5 * lane];
        #pragma unroll
        for (int k = 1; k < 5; k++) p = fmaxf(p, S[5 * lane + k]);
    }

    // ---- conv2: K=3 s=3 (30 -> 10), relu  (lanes 0..9 produce q)
    const float w20 = __ldg(&w2[0]), w21 = __ldg(&w2[1]), w22 = __ldg(&w2[2]);
    const float B2  = __ldg(b2);
    float pa = __shfl_sync(FULL, p, (3 * lane)     & 31);
    float pb = __shfl_sync(FULL, p, (3 * lane + 1) & 31);
    float pc = __shfl_sync(FULL, p, (3 * lane + 2) & 31);
    float q = fmaxf(fmaf(w20, pa, fmaf(w21, pb, fmaf(w22, pc, B2))), 0.0f);

    // ---- maxpool k=3 s=3 pad=1 (10 -> 4); relu no-op  (lanes 0..3)
    float qm = __shfl_sync(FULL, q, (3 * lane - 1) & 31);
    float q0 = __shfl_sync(FULL, q, (3 * lane)     & 31);
    float qp = __shfl_sync(FULL, q, (3 * lane + 1) & 31);
    float r;
    if (lane == 0)      r = fmaxf(q0, qp);        // window {-1(pad),0,1}
    else if (lane == 3) r = fmaxf(qm, q0);        // window {8,9,10(pad)}
    else                r = fmaxf(fmaxf(qm, q0), qp);

    // ---- conv3: K=4 s=1 (4 -> 1), relu -> feat
    float r0 = __shfl_sync(FULL, r, 0);
    float r1 = __shfl_sync(FULL, r, 1);
    float r2 = __shfl_sync(FULL, r, 2);
    float r3 = __shfl_sync(FULL, r, 3);
    if (lane == 0) {
        float f = __ldg(b3);
        f = fmaf(__ldg(&w3[0]), r0, f);
        f = fmaf(__ldg(&w3[1]), r1, f);
        f = fmaf(__ldg(&w3[2]), r2, f);
        f = fmaf(__ldg(&w3[3]), r3, f);
        g_feat[row] = fmaxf(f, 0.0f);
    }
}

// logits = feat @ cls_w.T + cls_b ; softmax over 3 classes. One block per batch.
__global__ __launch_bounds__(256) void head_kernel(
    const float* __restrict__ cw,   // [3,1024]
    const float* __restrict__ cb,   // [3]
    float* __restrict__ out)        // [64,3]
{
    const int b = blockIdx.x;
    const int t = threadIdx.x;
    const float4* f4 = reinterpret_cast<const float4*>(g_feat + b * 1024);
    const float4* c0 = reinterpret_cast<const float4*>(cw);
    const float4* c1 = reinterpret_cast<const float4*>(cw + 1024);
    const float4* c2 = reinterpret_cast<const float4*>(cw + 2048);

    float4 fv = f4[t];
    float4 w0 = c0[t], w1 = c1[t], w2 = c2[t];

    float a0 = fv.x * w0.x + fv.y * w0.y + fv.z * w0.z + fv.w * w0.w;
    float a1 = fv.x * w1.x + fv.y * w1.y + fv.z * w1.z + fv.w * w1.w;
    float a2 = fv.x * w2.x + fv.y * w2.y + fv.z * w2.z + fv.w * w2.w;

    #pragma unroll
    for (int o = 16; o > 0; o >>= 1) {
        a0 += __shfl_xor_sync(FULL, a0, o);
        a1 += __shfl_xor_sync(FULL, a1, o);
        a2 += __shfl_xor_sync(FULL, a2, o);
    }
    __shared__ float s[8][3];
    if ((t & 31) == 0) {
        int w = t >> 5;
        s[w][0] = a0; s[w][1] = a1; s[w][2] = a2;
    }
    __syncthreads();
    if (t == 0) {
        float l0 = __ldg(&cb[0]), l1 = __ldg(&cb[1]), l2 = __ldg(&cb[2]);
        #pragma unroll
        for (int w = 0; w < 8; w++) { l0 += s[w][0]; l1 += s[w][1]; l2 += s[w][2]; }
        float m  = fmaxf(l0, fmaxf(l1, l2));
        float e0 = expf(l0 - m), e1 = expf(l1 - m), e2 = expf(l2 - m);
        float inv = 1.0f / (e0 + e1 + e2);
        out[b * 3 + 0] = e0 * inv;
        out[b * 3 + 1] = e1 * inv;
        out[b * 3 + 2] = e2 * inv;
    }
}

extern "C" void kernel_launch(void* const* d_in, const int* in_sizes, int n_in,
                              void* d_out, int out_size)
{
    // metadata order: input, conv1_w, conv1_b, conv2_w, conv2_b, conv3_w,
    // conv3_b, gcn1_w, gcn1_b, gcn2_w, gcn2_b, cls_w, cls_b  (gcn* are dead)
    const float* x   = (const float*)d_in[0];
    const float* w1  = (const float*)d_in[1];
    const float* b1  = (const float*)d_in[2];
    const float* w2  = (const float*)d_in[3];
    const float* b2  = (const float*)d_in[4];
    const float* w3  = (const float*)d_in[5];
    const float* b3  = (const float*)d_in[6];
    const float* cw  = (const float*)d_in[11];
    const float* cb  = (const float*)d_in[12];
    float* out = (float*)d_out;

    conv_chain_kernel<<<8192, 256>>>(x, w1, b1, w2, b2, w3, b3);
    head_kernel<<<64, 256>>>(cw, cb, out);
}

// round 9
// speedup vs baseline: 1.5141x; 1.0170x over previous
#include <cuda_runtime.h>

#define FULL 0xFFFFFFFFu

// feat[b][n] scratch (64*1024 floats). __device__ global = allowed scratch.
__device__ float g_feat[64 * 1024];

// 6 blocks/SM min -> ptxas caps regs at 42 -> 48 warps/SM (75% occ).
__global__ __launch_bounds__(256, 6) void conv_chain_kernel(
    const float* __restrict__ x,
    const float* __restrict__ w1, const float* __restrict__ b1,
    const float* __restrict__ w2, const float* __restrict__ b2,
    const float* __restrict__ w3, const float* __restrict__ b3)
{
    // 8 warps per block, one row (b,n) per warp.
    __shared__ float sm[8][152];   // conv1 output for the 150->30 pool gather

    const int warp = threadIdx.x >> 5;
    const int lane = threadIdx.x & 31;
    const int row  = blockIdx.x * 8 + warp;   // row in [0, 65536)

    const float4* X4 = reinterpret_cast<const float4*>(x + (size_t)row * 1200);
    float* S = sm[warp];

    // ---- conv1: K=10, stride=8, pad=1, out length 150, relu.
    // Output j = 32*it + lane, window x[8j-1 .. 8j+8].
    // Depth-2 software pipeline: only 4 float4s live at a time (low regs ->
    // high occupancy), while keeping 4 LDG.128s in flight per lane.
    float4 a0, a1;
    {
        int jj = lane;                        // it=0: j = lane < 150 always
        a0 = X4[2 * jj];
        a1 = X4[2 * jj + 1];
    }

    float W1[10];
    #pragma unroll
    for (int k = 0; k < 10; k++) W1[k] = __ldg(&w1[k]);
    const float B1 = __ldg(b1);

    float carry = 0.0f;                       // x[8j-1] carry (x[-1] = pad)
    #pragma unroll
    for (int it = 0; it < 5; it++) {
        // prefetch next iteration's window
        float4 n0, n1;
        if (it < 4) {
            int j  = (it + 1) * 32 + lane;
            int jj = j < 150 ? j : 149;       // clamp (it==4 lanes 22..31 idle)
            n0 = X4[2 * jj];
            n1 = X4[2 * jj + 1];
        }

        // x[8j-1] = previous lane's a1.w
        float xm1 = __shfl_up_sync(FULL, a1.w, 1);
        if (lane == 0) xm1 = carry;
        carry = __shfl_sync(FULL, a1.w, 31);

        // x[8j+8] = next lane's a0.x; lane 31 takes next iter's lane-0 a0.x
        float nxt = (it < 4) ? __shfl_sync(FULL, n0.x, 0) : 0.0f;
        float a2  = __shfl_down_sync(FULL, a0.x, 1);
        if (lane == 31) a2 = nxt;
        int j = it * 32 + lane;
        if (j == 149) a2 = 0.0f;              // right pad

        float v = B1;
        v = fmaf(W1[0], xm1,  v);
        v = fmaf(W1[1], a0.x, v);
        v = fmaf(W1[2], a0.y, v);
        v = fmaf(W1[3], a0.z, v);
        v = fmaf(W1[4], a0.w, v);
        v = fmaf(W1[5], a1.x, v);
        v = fmaf(W1[6], a1.y, v);
        v = fmaf(W1[7], a1.z, v);
        v = fmaf(W1[8], a1.w, v);
        v = fmaf(W1[9], a2,   v);
        if (j < 150) S[j] = fmaxf(v, 0.0f);   // write y1 straight to smem

        a0 = n0; a1 = n1;
    }
    __syncwarp();

    // ---- maxpool k=5 s=5 (150 -> 30); relu no-op (inputs >= 0)
    float p = 0.0f;
    if (lane < 30) {
        p = S[5 * lane];
        #pragma unroll
        for (int k = 1; k < 5; k++) p = fmaxf(p, S[5 * lane + k]);
    }

    // ---- conv2: K=3 s=3 (30 -> 10), relu  (lanes 0..9 produce q)
    const float w20 = __ldg(&w2[0]), w21 = __ldg(&w2[1]), w22 = __ldg(&w2[2]);
    const float B2  = __ldg(b2);
    float pa = __shfl_sync(FULL, p, (3 * lane)     & 31);
    float pb = __shfl_sync(FULL, p, (3 * lane + 1) & 31);
    float pc = __shfl_sync(FULL, p, (3 * lane + 2) & 31);
    float q = fmaxf(fmaf(w20, pa, fmaf(w21, pb, fmaf(w22, pc, B2))), 0.0f);

    // ---- maxpool k=3 s=3 pad=1 (10 -> 4); relu no-op  (lanes 0..3)
    float qm = __shfl_sync(FULL, q, (3 * lane - 1) & 31);
    float q0 = __shfl_sync(FULL, q, (3 * lane)     & 31);
    float qp = __shfl_sync(FULL, q, (3 * lane + 1) & 31);
    float r;
    if (lane == 0)      r = fmaxf(q0, qp);        // window {-1(pad),0,1}
    else if (lane == 3) r = fmaxf(qm, q0);        // window {8,9,10(pad)}
    else                r = fmaxf(fmaxf(qm, q0), qp);

    // ---- conv3: K=4 s=1 (4 -> 1), relu -> feat
    float r0 = __shfl_sync(FULL, r, 0);
    float r1 = __shfl_sync(FULL, r, 1);
    float r2 = __shfl_sync(FULL, r, 2);
    float r3 = __shfl_sync(FULL, r, 3);
    if (lane == 0) {
        float f = __ldg(b3);
        f = fmaf(__ldg(&w3[0]), r0, f);
        f = fmaf(__ldg(&w3[1]), r1, f);
        f = fmaf(__ldg(&w3[2]), r2, f);
        f = fmaf(__ldg(&w3[3]), r3, f);
        g_feat[row] = fmaxf(f, 0.0f);
    }

#if __CUDA_ARCH__ >= 900
    // Allow the PDL-dependent head kernel to begin its prologue.
    cudaTriggerProgrammaticLaunchCompletion();
#endif
}

// logits = feat @ cls_w.T + cls_b ; softmax over 3 classes. One block per batch.
// Launched with programmatic stream serialization: starts during conv tail,
// loads cls_w (independent), then waits on the grid dependency before feat.
__global__ __launch_bounds__(256) void head_kernel(
    const float* __restrict__ cw,   // [3,1024]
    const float* __restrict__ cb,   // [3]
    float* __restrict__ out)        // [64,3]
{
    const int b = blockIdx.x;
    const int t = threadIdx.x;
    const float4* c0 = reinterpret_cast<const float4*>(cw);
    const float4* c1 = reinterpret_cast<const float4*>(cw + 1024);
    const float4* c2 = reinterpret_cast<const float4*>(cw + 2048);

    // Independent prologue: weight loads overlap the conv kernel's tail.
    float4 w0 = __ldg(&c0[t]);
    float4 w1 = __ldg(&c1[t]);
    float4 w2 = __ldg(&c2[t]);
    float cb0 = __ldg(&cb[0]), cb1 = __ldg(&cb[1]), cb2 = __ldg(&cb[2]);

#if __CUDA_ARCH__ >= 900
    cudaGridDependencySynchronize();   // wait for conv grid (g_feat ready)
#endif

    const float4* f4 = reinterpret_cast<const float4*>(g_feat + b * 1024);
    float4 fv = f4[t];

    float a0 = fv.x * w0.x + fv.y * w0.y + fv.z * w0.z + fv.w * w0.w;
    float a1 = fv.x * w1.x + fv.y * w1.y + fv.z * w1.z + fv.w * w1.w;
    float a2 = fv.x * w2.x + fv.y * w2.y + fv.z * w2.z + fv.w * w2.w;

    #pragma unroll
    for (int o = 16; o > 0; o >>= 1) {
        a0 += __shfl_xor_sync(FULL, a0, o);
        a1 += __shfl_xor_sync(FULL, a1, o);
        a2 += __shfl_xor_sync(FULL, a2, o);
    }
    __shared__ float s[8][3];
    if ((t & 31) == 0) {
        int w = t >> 5;
        s[w][0] = a0; s[w][1] = a1; s[w][2] = a2;
    }
    __syncthreads();
    if (t == 0) {
        float l0 = cb0, l1 = cb1, l2 = cb2;
        #pragma unroll
        for (int w = 0; w < 8; w++) { l0 += s[w][0]; l1 += s[w][1]; l2 += s[w][2]; }
        float m  = fmaxf(l0, fmaxf(l1, l2));
        float e0 = expf(l0 - m), e1 = expf(l1 - m), e2 = expf(l2 - m);
        float inv = 1.0f / (e0 + e1 + e2);
        out[b * 3 + 0] = e0 * inv;
        out[b * 3 + 1] = e1 * inv;
        out[b * 3 + 2] = e2 * inv;
    }
}

extern "C" void kernel_launch(void* const* d_in, const int* in_sizes, int n_in,
                              void* d_out, int out_size)
{
    // metadata order: input, conv1_w, conv1_b, conv2_w, conv2_b, conv3_w,
    // conv3_b, gcn1_w, gcn1_b, gcn2_w, gcn2_b, cls_w, cls_b  (gcn* are dead)
    const float* x   = (const float*)d_in[0];
    const float* w1  = (const float*)d_in[1];
    const float* b1  = (const float*)d_in[2];
    const float* w2  = (const float*)d_in[3];
    const float* b2  = (const float*)d_in[4];
    const float* w3  = (const float*)d_in[5];
    const float* b3  = (const float*)d_in[6];
    const float* cw  = (const float*)d_in[11];
    const float* cb  = (const float*)d_in[12];
    float* out = (float*)d_out;

    conv_chain_kernel<<<8192, 256>>>(x, w1, b1, w2, b2, w3, b3);

    // Head with programmatic dependent launch: overlaps its launch + weight
    // prologue with the conv tail; correctness guaranteed by
    // cudaGridDependencySynchronize() in the kernel.
    cudaLaunchAttribute attr[1];
    attr[0].id = cudaLaunchAttributeProgrammaticStreamSerialization;
    attr[0].val.programmaticStreamSerializationAllowed = 1;

    cudaLaunchConfig_t cfg = {};
    cfg.gridDim  = dim3(64, 1, 1);
    cfg.blockDim = dim3(256, 1, 1);
    cfg.dynamicSmemBytes = 0;
    cfg.stream = 0;          // legacy default stream (graph capture target)
    cfg.attrs = attr;
    cfg.numAttrs = 1;

    cudaError_t e = cudaLaunchKernelEx(&cfg, head_kernel, cw, cb, (float*)d_out);
    if (e != cudaSuccess) {
        // Fallback: plain launch (still correct, just no overlap).
        head_kernel<<<64, 256>>>(cw, cb, out);
    }
}